// round 5
// baseline (speedup 1.0000x reference)
#include <cuda_runtime.h>
#include <cstdint>

#define NN 25000        // nodes
#define NE 200000       // edges
#define C  32           // channels
#define CAP 32          // max degree capacity per node (Poisson(8) tail safe)

typedef unsigned long long u64;

// Mixed per-node features, packed: [node][c4][lane] float4
//   c4=0: {g0, g1x, g1y, g1z}; c4=1: {g2[0..3]}; c4=2: {g2[4..7]}; c4=3: {g2[8],0,0,0}
__device__ float4 g_mixed4[(size_t)NN * 4 * C];

// Slot-grouped-by-send edge data
__device__ int    g_counts[NN];
__device__ int    g_recv[(size_t)NN * CAP];
// attrs per slot: 4 float4 = {t,a1x,a1y,a1z}{a2 0..3}{a2 4..7}{a2 8, A01, A02, A12}
__device__ float4 g_attr[(size_t)NN * CAP * 4];

// ---------------------------------------------------------------------------
// f32x2 packed helpers
// ---------------------------------------------------------------------------
__device__ __forceinline__ u64 pk(float a, float b) {
    u64 r; asm("mov.b64 %0,{%1,%2};" : "=l"(r) : "f"(a), "f"(b)); return r;
}
__device__ __forceinline__ float2 upk(u64 v) {
    float2 f; asm("mov.b64 {%0,%1},%2;" : "=f"(f.x), "=f"(f.y) : "l"(v)); return f;
}
__device__ __forceinline__ u64 fma2(u64 a, u64 b, u64 c) {
    u64 r; asm("fma.rn.f32x2 %0,%1,%2,%3;" : "=l"(r) : "l"(a), "l"(b), "l"(c)); return r;
}
__device__ __forceinline__ u64 add2(u64 a, u64 b) {
    u64 r; asm("add.rn.f32x2 %0,%1,%2;" : "=l"(r) : "l"(a), "l"(b)); return r;
}

// ---------------------------------------------------------------------------
__global__ void zero_counts_kernel() {
    int i = blockIdx.x * blockDim.x + threadIdx.x;
    if (i < NN) g_counts[i] = 0;
}

// ---------------------------------------------------------------------------
// Merged kernel: first FILL_BLOCKS blocks scatter edges (+ packed attrs) into
// slots; remaining blocks do per-node channel mixing.
// ---------------------------------------------------------------------------
#define FILL_BLOCKS ((NE + 255) / 256)          // 782
#define MIX_BLOCKS  ((NN + 7) / 8)              // 3125

__global__ void __launch_bounds__(256) mixfill_kernel(
    const float* __restrict__ h0,   // [NN, C]
    const float* __restrict__ h1,   // [NN, C, 3]
    const float* __restrict__ h2,   // [NN, C, 3, 3]
    const float* __restrict__ W,    // [3, C, C]
    const int*   __restrict__ eidx, // [2, NE]
    const float* __restrict__ ea0,  // [NE]
    const float* __restrict__ ea1,  // [NE, 3]
    const float* __restrict__ ea2)  // [NE, 3, 3]
{
    if (blockIdx.x < FILL_BLOCKS) {
        // ---- fill path: group edges by send node, pack attrs in slot order ----
        int e = blockIdx.x * blockDim.x + threadIdx.x;
        if (e < NE) {
            int send = eidx[e];
            int recv = eidx[NE + e];
            float a0 = ea0[e];
            float a1x = ea1[e * 3 + 0], a1y = ea1[e * 3 + 1], a1z = ea1[e * 3 + 2];
            float a2[9];
#pragma unroll
            for (int m = 0; m < 9; m++) a2[m] = ea2[e * 9 + m];
            float t = a0 + a2[0] + a2[4] + a2[8];

            int pos = atomicAdd(&g_counts[send], 1);
            if (pos < CAP) {
                size_t slot = (size_t)send * CAP + pos;
                g_recv[slot] = recv;
                float4* ap = g_attr + slot * 4;
                ap[0] = make_float4(t, a1x, a1y, a1z);
                ap[1] = make_float4(a2[0], a2[1], a2[2], a2[3]);
                ap[2] = make_float4(a2[4], a2[5], a2[6], a2[7]);
                ap[3] = make_float4(a2[8], a2[1] + a2[3], a2[2] + a2[6], a2[5] + a2[7]);
            }
        }
        return;
    }

    // ---- mix path: g[r][n,i,x] = sum_j W[r][i,j] * h[r][n,j,x] ----
    __shared__ float sW[3 * C * C]; // transposed: sW[r*1024 + j*32 + i] = W[r][i][j]
    for (int idx = threadIdx.x; idx < 3 * C * C; idx += blockDim.x) {
        int r = idx >> 10;
        int rem = idx & 1023;
        int i = rem >> 5;
        int j = rem & 31;
        sW[(r << 10) + (j << 5) + i] = W[idx];
    }
    __syncthreads();

    const int lane = threadIdx.x & 31;
    const int n = (blockIdx.x - FILL_BLOCKS) * (blockDim.x >> 5) + (threadIdx.x >> 5);
    if (n >= NN) return;

    float v0 = h0[n * C + lane];
    float v1[3], v2[9];
#pragma unroll
    for (int d = 0; d < 3; d++) v1[d] = h1[n * (C * 3) + lane * 3 + d];
#pragma unroll
    for (int m = 0; m < 9; m++) v2[m] = h2[n * (C * 9) + lane * 9 + m];

    float o0 = 0.f;
    float o1[3] = {0.f, 0.f, 0.f};
    float o2[9] = {0.f, 0.f, 0.f, 0.f, 0.f, 0.f, 0.f, 0.f, 0.f};

#pragma unroll 8
    for (int j = 0; j < C; j++) {
        float w0 = sW[(j << 5) + lane];
        float w1 = sW[1024 + (j << 5) + lane];
        float w2 = sW[2048 + (j << 5) + lane];
        o0 += w0 * __shfl_sync(0xffffffffu, v0, j);
#pragma unroll
        for (int d = 0; d < 3; d++)
            o1[d] += w1 * __shfl_sync(0xffffffffu, v1[d], j);
#pragma unroll
        for (int m = 0; m < 9; m++)
            o2[m] += w2 * __shfl_sync(0xffffffffu, v2[m], j);
    }

    float4* gp = g_mixed4 + (size_t)n * (4 * C);
    gp[0 * C + lane] = make_float4(o0, o1[0], o1[1], o1[2]);
    gp[1 * C + lane] = make_float4(o2[0], o2[1], o2[2], o2[3]);
    gp[2 * C + lane] = make_float4(o2[4], o2[5], o2[6], o2[7]);
    gp[3 * C + lane] = make_float4(o2[8], 0.f, 0.f, 0.f);
}

// ---------------------------------------------------------------------------
// Packed-pair contraction core: edges A,B packed in f32x2 lanes of u64 regs.
// acc: [0]=rank0, [1..3]=rank1, [4..12]=rank2
// ---------------------------------------------------------------------------
__device__ __forceinline__ void contract_pair(
    const float4& vA0, const float4& vA1, const float4& vA2, const float4& vA3,
    const float4& vB0, const float4& vB1, const float4& vB2, const float4& vB3,
    const float4& pA0, const float4& pA1, const float4& pA2, const float4& pA3,
    const float4& pB0, const float4& pB1, const float4& pB2, const float4& pB3,
    u64* acc)
{
    // g-side packed
    u64 G0 = pk(vA0.x, vB0.x);
    u64 G1[3] = { pk(vA0.y, vB0.y), pk(vA0.z, vB0.z), pk(vA0.w, vB0.w) };
    u64 G2[9] = { pk(vA1.x, vB1.x), pk(vA1.y, vB1.y), pk(vA1.z, vB1.z),
                  pk(vA1.w, vB1.w), pk(vA2.x, vB2.x), pk(vA2.y, vB2.y),
                  pk(vA2.z, vB2.z), pk(vA2.w, vB2.w), pk(vA3.x, vB3.x) };

    // a-side packed
    u64 T = pk(pA0.x, pB0.x);
    u64 A1[3] = { pk(pA0.y, pB0.y), pk(pA0.z, pB0.z), pk(pA0.w, pB0.w) };
    u64 Q2[9] = { pk(pA1.x, pB1.x), pk(pA1.y, pB1.y), pk(pA1.z, pB1.z),
                  pk(pA1.w, pB1.w), pk(pA2.x, pB2.x), pk(pA2.y, pB2.y),
                  pk(pA2.z, pB2.z), pk(pA2.w, pB2.w), pk(pA3.x, pB3.x) };
    u64 Ao01 = pk(pA3.y, pB3.y), Ao02 = pk(pA3.z, pB3.z), Ao12 = pk(pA3.w, pB3.w);

    // A2 = a2 + a2^T (offdiags precomputed in fill)
    u64 A[9];
    A[0] = add2(Q2[0], Q2[0]); A[4] = add2(Q2[4], Q2[4]); A[8] = add2(Q2[8], Q2[8]);
    A[1] = Ao01; A[3] = Ao01; A[2] = Ao02; A[6] = Ao02; A[5] = Ao12; A[7] = Ao12;

    // S2 = g2 + g2^T
    u64 S[9];
    S[0] = add2(G2[0], G2[0]); S[4] = add2(G2[4], G2[4]); S[8] = add2(G2[8], G2[8]);
    u64 So01 = add2(G2[1], G2[3]); S[1] = So01; S[3] = So01;
    u64 So02 = add2(G2[2], G2[6]); S[2] = So02; S[6] = So02;
    u64 So12 = add2(G2[5], G2[7]); S[5] = So12; S[7] = So12;

    u64 trg = add2(G2[0], add2(G2[4], G2[8]));
    u64 s = add2(G0, trg);

    // rank-0: s*t + g1.a1 + sum(S2 .* a2)
    acc[0] = fma2(s, T, acc[0]);
#pragma unroll
    for (int k = 0; k < 3; k++) acc[0] = fma2(G1[k], A1[k], acc[0]);
#pragma unroll
    for (int m = 0; m < 9; m++) acc[0] = fma2(S[m], Q2[m], acc[0]);

    // rank-1: s*a1 + t*g1 + A2*g1 + S2*a1
#pragma unroll
    for (int d = 0; d < 3; d++) {
        u64 a = acc[1 + d];
        a = fma2(s, A1[d], a);
        a = fma2(T, G1[d], a);
#pragma unroll
        for (int k = 0; k < 3; k++) {
            a = fma2(A[3 * d + k], G1[k], a);
            a = fma2(S[3 * d + k], A1[k], a);
        }
        acc[1 + d] = a;
    }

    // rank-2: s*a2 + g1 outer a1 + t*g2 + S2 * A2^T
#pragma unroll
    for (int d = 0; d < 3; d++)
#pragma unroll
        for (int k = 0; k < 3; k++) {
            u64 a = acc[4 + 3 * d + k];
            a = fma2(s, Q2[3 * d + k], a);
            a = fma2(G1[d], A1[k], a);
            a = fma2(T, G2[3 * d + k], a);
#pragma unroll
            for (int m = 0; m < 3; m++)
                a = fma2(S[3 * d + m], A[3 * k + m], a);
            acc[4 + 3 * d + k] = a;
        }
}

// ---------------------------------------------------------------------------
// Gather-reduce: one warp per node, lane = channel, 2 edges per iteration
// via f32x2 packing. No atomics, no output zeroing.
// ---------------------------------------------------------------------------
__global__ void __launch_bounds__(256) reduce_kernel(float* __restrict__ out)
{
    const int lane = threadIdx.x & 31;
    const int node = blockIdx.x * (blockDim.x >> 5) + (threadIdx.x >> 5);
    if (node >= NN) return;

    int cnt = g_counts[node];
    if (cnt > CAP) cnt = CAP;
    const int*    rp = g_recv + (size_t)node * CAP;
    const float4* ap = g_attr + (size_t)node * CAP * 4;

    u64 acc[13];
#pragma unroll
    for (int i = 0; i < 13; i++) acc[i] = 0ull;

    int p = 0;
    for (; p + 1 < cnt; p += 2) {
        int rA = rp[p], rB = rp[p + 1];
        const float4* gA = g_mixed4 + (size_t)rA * (4 * C);
        const float4* gB = g_mixed4 + (size_t)rB * (4 * C);
        // 8 independent 128-bit gathers + 8 uniform attr loads
        float4 vA0 = gA[0 * C + lane], vA1 = gA[1 * C + lane];
        float4 vA2 = gA[2 * C + lane], vA3 = gA[3 * C + lane];
        float4 vB0 = gB[0 * C + lane], vB1 = gB[1 * C + lane];
        float4 vB2 = gB[2 * C + lane], vB3 = gB[3 * C + lane];
        float4 pA0 = ap[p * 4 + 0], pA1 = ap[p * 4 + 1];
        float4 pA2 = ap[p * 4 + 2], pA3 = ap[p * 4 + 3];
        float4 pB0 = ap[p * 4 + 4], pB1 = ap[p * 4 + 5];
        float4 pB2 = ap[p * 4 + 6], pB3 = ap[p * 4 + 7];

        contract_pair(vA0, vA1, vA2, vA3, vB0, vB1, vB2, vB3,
                      pA0, pA1, pA2, pA3, pB0, pB1, pB2, pB3, acc);
    }
    if (p < cnt) {
        // odd tail: edge B = zero attrs (all terms carry an a-factor -> 0)
        int rA = rp[p];
        const float4* gA = g_mixed4 + (size_t)rA * (4 * C);
        float4 vA0 = gA[0 * C + lane], vA1 = gA[1 * C + lane];
        float4 vA2 = gA[2 * C + lane], vA3 = gA[3 * C + lane];
        float4 pA0 = ap[p * 4 + 0], pA1 = ap[p * 4 + 1];
        float4 pA2 = ap[p * 4 + 2], pA3 = ap[p * 4 + 3];
        float4 z = make_float4(0.f, 0.f, 0.f, 0.f);

        contract_pair(vA0, vA1, vA2, vA3, vA0, vA1, vA2, vA3,
                      pA0, pA1, pA2, pA3, z, z, z, z, acc);
    }

    // combine packed halves, write each output element exactly once
    float2 r0 = upk(acc[0]);
    out[(size_t)node * C + lane] = r0.x + r0.y;
    float* o1base = out + (size_t)NN * C + ((size_t)node * C + lane) * 3;
#pragma unroll
    for (int d = 0; d < 3; d++) {
        float2 r = upk(acc[1 + d]);
        o1base[d] = r.x + r.y;
    }
    float* o2base = out + (size_t)NN * C * 4 + ((size_t)node * C + lane) * 9;
#pragma unroll
    for (int m = 0; m < 9; m++) {
        float2 r = upk(acc[4 + m]);
        o2base[m] = r.x + r.y;
    }
}

// ---------------------------------------------------------------------------
extern "C" void kernel_launch(void* const* d_in, const int* in_sizes, int n_in,
                              void* d_out, int out_size) {
    const float* h0  = (const float*)d_in[0];
    const float* h1  = (const float*)d_in[1];
    const float* h2  = (const float*)d_in[2];
    // d_in[3] = rel_pos (unused by the math)
    const float* ea0 = (const float*)d_in[4];
    const float* ea1 = (const float*)d_in[5];
    const float* ea2 = (const float*)d_in[6];
    const float* W   = (const float*)d_in[7];
    const int*   eidx = (const int*)d_in[8];
    float* out = (float*)d_out;

    zero_counts_kernel<<<(NN + 255) / 256, 256>>>();
    mixfill_kernel<<<FILL_BLOCKS + MIX_BLOCKS, 256>>>(h0, h1, h2, W, eidx, ea0, ea1, ea2);
    reduce_kernel<<<(NN + 7) / 8, 256>>>(out);
}